// round 13
// baseline (speedup 1.0000x reference)
#include <cuda_runtime.h>
#include <cuda_bf16.h>

// ModernBertCanonLayer: varlen depthwise conv (K=5) + bias + residual.
// Round-12: cp.async (LDGSTS) deep pipeline into a 32-row circular SMEM
// buffer. In-flight bytes decoupled from registers/warps: up to 5 pending
// 4-row chunks (60KB) per CTA. Each thread owns one 16B column -> no
// __syncthreads in the mainloop. 192-thread CTAs, 2/SM, grid = 2 waves.

#define CCH   768
#define C4    (CCH / 4)      // 192 float4 per row
#define ROWB  3072           // bytes per staged row
#define NROW  32             // circular rows (8 chunks x 4 rows), power of 2
#define SMEM_BYTES (NROW * ROWB)   // 98304
#define GRID  592            // 2 exact waves of 296 resident CTAs (2/SM)
#define NSTREAMS GRID

#define FMA4(acc, wk, r)                                   \
    acc.x = fmaf((wk)[0], (r).x, acc.x);                   \
    acc.y = fmaf((wk)[1], (r).y, acc.y);                   \
    acc.z = fmaf((wk)[2], (r).z, acc.z);                   \
    acc.w = fmaf((wk)[3], (r).w, acc.w);

#define FMA4M(acc, wk, r, m)                               \
    acc.x = fmaf((m) ? (wk)[0] : 0.f, (r).x, acc.x);       \
    acc.y = fmaf((m) ? (wk)[1] : 0.f, (r).y, acc.y);       \
    acc.z = fmaf((m) ? (wk)[2] : 0.f, (r).z, acc.z);       \
    acc.w = fmaf((m) ? (wk)[3] : 0.f, (r).w, acc.w);

#define TOKEN_FAST(po, A0, A1, A2, A3, A4)                 \
    do {                                                   \
        float4 acc = b4;                                   \
        FMA4(acc, w[0], A0); FMA4(acc, w[1], A1);          \
        FMA4(acc, w[2], A2); FMA4(acc, w[3], A3);          \
        FMA4(acc, w[4], A4);                               \
        float4 o;                                          \
        o.x = (A2).x + acc.x; o.y = (A2).y + acc.y;        \
        o.z = (A2).z + acc.z; o.w = (A2).w + acc.w;        \
        __stcs((po), o);                                   \
    } while (0)

#define TOKEN_SLOW(it, po, A0, A1, A2, A3, A4)             \
    do {                                                   \
        while ((it) >= hhi) { ++ss; llo = s_cu[ss]; hhi = s_cu[ss + 1]; } \
        float4 acc = b4;                                   \
        FMA4M(acc, w[0], A0, (it) - 2 >= llo);             \
        FMA4M(acc, w[1], A1, (it) - 1 >= llo);             \
        FMA4(acc, w[2], A2);                               \
        FMA4M(acc, w[3], A3, (it) + 1 < hhi);              \
        FMA4M(acc, w[4], A4, (it) + 2 < hhi);              \
        float4 o;                                          \
        o.x = (A2).x + acc.x; o.y = (A2).y + acc.y;        \
        o.z = (A2).z + acc.z; o.w = (A2).w + acc.w;        \
        __stcs((po), o);                                   \
    } while (0)

__device__ __forceinline__ void cpa16(unsigned int dst, const void* src) {
    asm volatile("cp.async.cg.shared.global [%0], [%1], 16;"
                 :: "r"(dst), "l"(src) : "memory");
}
__device__ __forceinline__ void cpa_commit() {
    asm volatile("cp.async.commit_group;" ::: "memory");
}
#define CPA_WAIT(n) asm volatile("cp.async.wait_group %0;" :: "n"(n) : "memory")

__global__ __launch_bounds__(C4, 2)
void canon_kernel(const float* __restrict__ x,
                  const int*   __restrict__ cu, int ncu,
                  const float* __restrict__ weight,
                  const float* __restrict__ bias,
                  float*       __restrict__ out,
                  int T)
{
    extern __shared__ float4 sbuf[];       // NROW x C4 float4 circular buffer
    __shared__ int s_cu[64];
    if (threadIdx.x < ncu) s_cu[threadIdx.x] = cu[threadIdx.x];
    __syncthreads();

    const int c4 = threadIdx.x;            // 0..191 (this thread's column)
    const int S  = blockIdx.x;

    // Balanced token split (lengths differ by at most 1).
    const int Lsmall = T / NSTREAMS;
    const int R      = T - Lsmall * NSTREAMS;
    const int len    = Lsmall + (S < R ? 1 : 0);
    const int base   = S * Lsmall + (S < R ? S : R);
    if (len <= 0) return;

    float w[5][4];
    {
        const int c0 = c4 * 4;
        #pragma unroll
        for (int j = 0; j < 4; ++j)
            #pragma unroll
            for (int k = 0; k < 5; ++k)
                w[k][j] = weight[(c0 + j) * 5 + k];
    }
    const float4 b4 = reinterpret_cast<const float4*>(bias)[c4];

    const float4* __restrict__ x4 = reinterpret_cast<const float4*>(x);
    float4* __restrict__       o4 = reinterpret_cast<float4*>(out);

    const int tmax = T - 1;
    const unsigned int sb =
        (unsigned int)__cvta_generic_to_shared(sbuf) + (unsigned int)c4 * 16u;

    // Produce chunk c: rows q = 4c..4c+3 (q is row index relative to base-2),
    // source row clamped to [0, tmax] (garbage rows are masked at compute).
    auto produce = [&](int c) {
        #pragma unroll
        for (int r = 0; r < 4; ++r) {
            int q = 4 * c + r;
            int j = base - 2 + q;
            j = j < 0 ? 0 : (j > tmax ? tmax : j);
            cpa16(sb + (unsigned int)(q & (NROW - 1)) * ROWB,
                  x4 + (size_t)j * C4 + c4);
        }
        cpa_commit();
    };

    // Prologue: fill all 8 chunks (rows base-2 .. base+29, clamped).
    #pragma unroll
    for (int c = 0; c < 8; ++c) produce(c);

    // Segment of token `base` (searchsorted-right; handles empty sequences).
    int s = 0;
    while (base >= s_cu[s + 1]) ++s;
    int lo = s_cu[s], hi = s_cu[s + 1];

    // Initial window r0..r4 = rows base-2 .. base+2 (q = 0..4; chunks 0,1).
    CPA_WAIT(5);                          // chunks 0..2 arrived
    float4 r0 = sbuf[(0 & (NROW - 1)) * C4 + c4];
    float4 r1 = sbuf[(1 & (NROW - 1)) * C4 + c4];
    float4 r2 = sbuf[(2 & (NROW - 1)) * C4 + c4];
    float4 r3 = sbuf[(3 & (NROW - 1)) * C4 + c4];
    float4 r4 = sbuf[(4 & (NROW - 1)) * C4 + c4];

    const int iend = base + len;
    int i = base, g = 0;
    float4* po = o4 + (size_t)i * C4 + c4;

    // ---- main loop: consume chunks g+1/g+2, produce chunk g+8 ----
    for (; i + 3 < iend; i += 4, ++g) {
        // committed = 8+g; wait 5 pending -> chunks 0..g+2 arrived
        CPA_WAIT(5);

        const int qn = 4 * g + 5;         // row i+3
        float4 n0 = sbuf[((qn    ) & (NROW - 1)) * C4 + c4];
        float4 n1 = sbuf[((qn + 1) & (NROW - 1)) * C4 + c4];
        float4 n2 = sbuf[((qn + 2) & (NROW - 1)) * C4 + c4];
        float4 n3 = sbuf[((qn + 3) & (NROW - 1)) * C4 + c4];

        produce(g + 8);                   // rows i+30..i+33 (clamped)

        while (i >= hi) { ++s; lo = s_cu[s]; hi = s_cu[s + 1]; }

        if (i - 2 >= lo && i + 5 < hi) {
            TOKEN_FAST(po         , r0, r1, r2, r3, r4);
            TOKEN_FAST(po + C4    , r1, r2, r3, r4, n0);
            TOKEN_FAST(po + 2 * C4, r2, r3, r4, n0, n1);
            TOKEN_FAST(po + 3 * C4, r3, r4, n0, n1, n2);
        } else {
            int ss = s, llo = lo, hhi = hi;
            TOKEN_SLOW(i    , po         , r0, r1, r2, r3, r4);
            TOKEN_SLOW(i + 1, po + C4    , r1, r2, r3, r4, n0);
            TOKEN_SLOW(i + 2, po + 2 * C4, r2, r3, r4, n0, n1);
            TOKEN_SLOW(i + 3, po + 3 * C4, r3, r4, n0, n1, n2);
        }

        r0 = r4; r1 = n0; r2 = n1; r3 = n2; r4 = n3;
        po += 4 * C4;
    }

    // ---- tail (<= 3 tokens): rows already staged; drain the pipe ----
    CPA_WAIT(0);
    for (; i < iend; ++i) {
        while (i >= hi) { ++s; lo = s_cu[s]; hi = s_cu[s + 1]; }
        int ss = s, llo = lo, hhi = hi;
        TOKEN_SLOW(i, po, r0, r1, r2, r3, r4);
        const int qn = (i + 3) - base + 2;            // row i+3
        float4 nn = sbuf[(qn & (NROW - 1)) * C4 + c4];
        r0 = r1; r1 = r2; r2 = r3; r3 = r4; r4 = nn;
        po += C4;
    }
}

extern "C" void kernel_launch(void* const* d_in, const int* in_sizes, int n_in,
                              void* d_out, int out_size)
{
    const float* x      = (const float*)d_in[0];
    const int*   cu     = (const int*)  d_in[1];
    const float* weight = (const float*)d_in[2];
    const float* bias   = (const float*)d_in[3];
    float*       out    = (float*)d_out;

    const int T   = in_sizes[0] / CCH;
    const int ncu = in_sizes[1];

    cudaFuncSetAttribute(canon_kernel,
                         cudaFuncAttributeMaxDynamicSharedMemorySize,
                         SMEM_BYTES);
    canon_kernel<<<GRID, C4, SMEM_BYTES>>>(x, cu, ncu, weight, bias, out, T);
}

// round 14
// speedup vs baseline: 1.0403x; 1.0403x over previous
#include <cuda_runtime.h>
#include <cuda_bf16.h>

// ModernBertCanonLayer: varlen depthwise conv (K=5) + bias + residual.
// Round-13: R12 cp.async deep pipeline + stream-end clamp on staged rows.
// R12 overfetched ~22% of reads past each stream's end; staging clamps to
// lastrow = min(iend+1, T-1) so every DRAM byte fetched is consumed.

#define CCH   768
#define C4    (CCH / 4)      // 192 float4 per row
#define ROWB  3072           // bytes per staged row
#define NROW  32             // circular rows (8 chunks x 4 rows), power of 2
#define SMEM_BYTES (NROW * ROWB)   // 98304
#define GRID  592            // 2 exact waves of 296 resident CTAs (2/SM)
#define NSTREAMS GRID

#define FMA4(acc, wk, r)                                   \
    acc.x = fmaf((wk)[0], (r).x, acc.x);                   \
    acc.y = fmaf((wk)[1], (r).y, acc.y);                   \
    acc.z = fmaf((wk)[2], (r).z, acc.z);                   \
    acc.w = fmaf((wk)[3], (r).w, acc.w);

#define FMA4M(acc, wk, r, m)                               \
    acc.x = fmaf((m) ? (wk)[0] : 0.f, (r).x, acc.x);       \
    acc.y = fmaf((m) ? (wk)[1] : 0.f, (r).y, acc.y);       \
    acc.z = fmaf((m) ? (wk)[2] : 0.f, (r).z, acc.z);       \
    acc.w = fmaf((m) ? (wk)[3] : 0.f, (r).w, acc.w);

#define TOKEN_FAST(po, A0, A1, A2, A3, A4)                 \
    do {                                                   \
        float4 acc = b4;                                   \
        FMA4(acc, w[0], A0); FMA4(acc, w[1], A1);          \
        FMA4(acc, w[2], A2); FMA4(acc, w[3], A3);          \
        FMA4(acc, w[4], A4);                               \
        float4 o;                                          \
        o.x = (A2).x + acc.x; o.y = (A2).y + acc.y;        \
        o.z = (A2).z + acc.z; o.w = (A2).w + acc.w;        \
        __stcs((po), o);                                   \
    } while (0)

#define TOKEN_SLOW(it, po, A0, A1, A2, A3, A4)             \
    do {                                                   \
        while ((it) >= hhi) { ++ss; llo = s_cu[ss]; hhi = s_cu[ss + 1]; } \
        float4 acc = b4;                                   \
        FMA4M(acc, w[0], A0, (it) - 2 >= llo);             \
        FMA4M(acc, w[1], A1, (it) - 1 >= llo);             \
        FMA4(acc, w[2], A2);                               \
        FMA4M(acc, w[3], A3, (it) + 1 < hhi);              \
        FMA4M(acc, w[4], A4, (it) + 2 < hhi);              \
        float4 o;                                          \
        o.x = (A2).x + acc.x; o.y = (A2).y + acc.y;        \
        o.z = (A2).z + acc.z; o.w = (A2).w + acc.w;        \
        __stcs((po), o);                                   \
    } while (0)

__device__ __forceinline__ void cpa16(unsigned int dst, const void* src) {
    asm volatile("cp.async.cg.shared.global [%0], [%1], 16;"
                 :: "r"(dst), "l"(src) : "memory");
}
__device__ __forceinline__ void cpa_commit() {
    asm volatile("cp.async.commit_group;" ::: "memory");
}
#define CPA_WAIT(n) asm volatile("cp.async.wait_group %0;" :: "n"(n) : "memory")

__global__ __launch_bounds__(C4, 2)
void canon_kernel(const float* __restrict__ x,
                  const int*   __restrict__ cu, int ncu,
                  const float* __restrict__ weight,
                  const float* __restrict__ bias,
                  float*       __restrict__ out,
                  int T)
{
    extern __shared__ float4 sbuf[];       // NROW x C4 float4 circular buffer
    __shared__ int s_cu[64];
    if (threadIdx.x < ncu) s_cu[threadIdx.x] = cu[threadIdx.x];
    __syncthreads();

    const int c4 = threadIdx.x;            // 0..191 (this thread's column)
    const int S  = blockIdx.x;

    // Balanced token split (lengths differ by at most 1).
    const int Lsmall = T / NSTREAMS;
    const int R      = T - Lsmall * NSTREAMS;
    const int len    = Lsmall + (S < R ? 1 : 0);
    const int base   = S * Lsmall + (S < R ? S : R);
    if (len <= 0) return;

    float w[5][4];
    {
        const int c0 = c4 * 4;
        #pragma unroll
        for (int j = 0; j < 4; ++j)
            #pragma unroll
            for (int k = 0; k < 5; ++k)
                w[k][j] = weight[(c0 + j) * 5 + k];
    }
    const float4 b4 = reinterpret_cast<const float4*>(bias)[c4];

    const float4* __restrict__ x4 = reinterpret_cast<const float4*>(x);
    float4* __restrict__       o4 = reinterpret_cast<float4*>(out);

    const int iend    = base + len;
    // Deepest row any token of THIS stream can consume is iend+1; clamping
    // there (and at T-1) makes every staged load a useful (or L2-dup) byte.
    const int tclamp  = (iend + 1 < T) ? (iend + 1) : (T - 1);

    const unsigned int sb =
        (unsigned int)__cvta_generic_to_shared(sbuf) + (unsigned int)c4 * 16u;

    // Produce chunk c: rows q = 4c..4c+3 (q relative to base-2), source row
    // clamped to [0, tclamp]; garbage rows are masked at compute.
    auto produce = [&](int c) {
        #pragma unroll
        for (int r = 0; r < 4; ++r) {
            int q = 4 * c + r;
            int j = base - 2 + q;
            j = j < 0 ? 0 : (j > tclamp ? tclamp : j);
            cpa16(sb + (unsigned int)(q & (NROW - 1)) * ROWB,
                  x4 + (size_t)j * C4 + c4);
        }
        cpa_commit();
    };

    // Prologue: fill all 8 chunks (rows base-2 .. base+29, clamped).
    #pragma unroll
    for (int c = 0; c < 8; ++c) produce(c);

    // Segment of token `base` (searchsorted-right; handles empty sequences).
    int s = 0;
    while (base >= s_cu[s + 1]) ++s;
    int lo = s_cu[s], hi = s_cu[s + 1];

    // Initial window r0..r4 = rows base-2 .. base+2 (q = 0..4; chunks 0,1).
    CPA_WAIT(5);                          // chunks 0..2 arrived
    float4 r0 = sbuf[0 * C4 + c4];
    float4 r1 = sbuf[1 * C4 + c4];
    float4 r2 = sbuf[2 * C4 + c4];
    float4 r3 = sbuf[3 * C4 + c4];
    float4 r4 = sbuf[4 * C4 + c4];

    int i = base, g = 0;
    float4* po = o4 + (size_t)i * C4 + c4;

    // ---- main loop: consume rows of chunks g+1/g+2, produce chunk g+8 ----
    for (; i + 3 < iend; i += 4, ++g) {
        // committed = 8+g groups; wait 5 pending -> chunks 0..g+2 arrived
        CPA_WAIT(5);

        const int qn = 4 * g + 5;         // row i+3
        float4 n0 = sbuf[((qn    ) & (NROW - 1)) * C4 + c4];
        float4 n1 = sbuf[((qn + 1) & (NROW - 1)) * C4 + c4];
        float4 n2 = sbuf[((qn + 2) & (NROW - 1)) * C4 + c4];
        float4 n3 = sbuf[((qn + 3) & (NROW - 1)) * C4 + c4];

        produce(g + 8);                   // rows i+30..i+33 (clamped to stream)

        while (i >= hi) { ++s; lo = s_cu[s]; hi = s_cu[s + 1]; }

        if (i - 2 >= lo && i + 5 < hi) {
            TOKEN_FAST(po         , r0, r1, r2, r3, r4);
            TOKEN_FAST(po + C4    , r1, r2, r3, r4, n0);
            TOKEN_FAST(po + 2 * C4, r2, r3, r4, n0, n1);
            TOKEN_FAST(po + 3 * C4, r3, r4, n0, n1, n2);
        } else {
            int ss = s, llo = lo, hhi = hi;
            TOKEN_SLOW(i    , po         , r0, r1, r2, r3, r4);
            TOKEN_SLOW(i + 1, po + C4    , r1, r2, r3, r4, n0);
            TOKEN_SLOW(i + 2, po + 2 * C4, r2, r3, r4, n0, n1);
            TOKEN_SLOW(i + 3, po + 3 * C4, r3, r4, n0, n1, n2);
        }

        r0 = r4; r1 = n0; r2 = n1; r3 = n2; r4 = n3;
        po += 4 * C4;
    }

    // ---- tail (<= 3 tokens): rows already staged; drain the pipe ----
    CPA_WAIT(0);
    for (; i < iend; ++i) {
        while (i >= hi) { ++s; lo = s_cu[s]; hi = s_cu[s + 1]; }
        int ss = s, llo = lo, hhi = hi;
        TOKEN_SLOW(i, po, r0, r1, r2, r3, r4);
        const int qn = (i + 3) - base + 2;            // row i+3
        float4 nn = sbuf[(qn & (NROW - 1)) * C4 + c4];
        r0 = r1; r1 = r2; r2 = r3; r3 = r4; r4 = nn;
        po += C4;
    }
}

extern "C" void kernel_launch(void* const* d_in, const int* in_sizes, int n_in,
                              void* d_out, int out_size)
{
    const float* x      = (const float*)d_in[0];
    const int*   cu     = (const int*)  d_in[1];
    const float* weight = (const float*)d_in[2];
    const float* bias   = (const float*)d_in[3];
    float*       out    = (float*)d_out;

    const int T   = in_sizes[0] / CCH;
    const int ncu = in_sizes[1];

    cudaFuncSetAttribute(canon_kernel,
                         cudaFuncAttributeMaxDynamicSharedMemorySize,
                         SMEM_BYTES);
    canon_kernel<<<GRID, C4, SMEM_BYTES>>>(x, cu, ncu, weight, bias, out, T);
}